// round 12
// baseline (speedup 1.0000x reference)
#include <cuda_runtime.h>
#include <cstdint>

// TSK fuzzy system via mma.sync tf32 tensor ops (baseline sm_80+ ISA).
// out[n] = sum_r fg_bar[n,r]*(x[n]·W[r]+b[r]); fg_bar separable-normalized.
// Per CTA: tile of 128 samples x TWO groups of 512 rules (sequential):
//   D[128x16] += FG[128x512] @ Wb^T,  Wb[r] = [W[r][0..7], b[r], 0,...]
// FG fragments generated in registers; raw f32 bits fed to HMMA (HW tf32
// truncation — no per-element cvt). Wb^T fragments built straight from gmem.

#define NSAMP 1024
#define NGY 64       // grid.y; each CTA does 2 rule groups -> 128 groups
#define NGROUP 128
#define TILES 8      // grid.x: sample tiles of 128

#define SM_MG_OFF 32768
#define SMEM_TOTAL (32768 + 16896)

__device__ float g_part[NGROUP * 9 * NSAMP];  // [g][k][n]
__device__ float g_A[9 * NSAMP];              // [k][n] reduced

__device__ __forceinline__ uint32_t tf32r(float f) {
    uint32_t r; asm("cvt.rna.tf32.f32 %0, %1;" : "=r"(r) : "f"(f)); return r;
}
__device__ __forceinline__ void mma8(float* d, uint32_t a0, uint32_t a1,
                                     uint32_t a2, uint32_t a3,
                                     uint32_t b0, uint32_t b1) {
    asm volatile(
        "mma.sync.aligned.m16n8k8.row.col.f32.tf32.tf32.f32 "
        "{%0,%1,%2,%3}, {%4,%5,%6,%7}, {%8,%9}, {%0,%1,%2,%3};"
        : "+f"(d[0]), "+f"(d[1]), "+f"(d[2]), "+f"(d[3])
        : "r"(a0), "r"(a1), "r"(a2), "r"(a3), "r"(b0), "r"(b1));
}

__global__ __launch_bounds__(128) void tsk_kernel(
    const float* __restrict__ x, const float* __restrict__ center,
    const float* __restrict__ sigma, const float* __restrict__ W,
    const float* __restrict__ b)
{
    extern __shared__ __align__(16) unsigned char dynsm[];
    uint2* smB = reinterpret_cast<uint2*>(dynsm);               // B fragments
    float* s_mg = reinterpret_cast<float*>(dynsm + SM_MG_OFF);  // memberships

    int tid = threadIdx.x, lane = tid & 31, w = tid >> 5;
    int tile = blockIdx.x;

    // ---- memberships: one thread per sample, [s][33] padded ----
    {
        int n = tile * 128 + tid;
        float* row = s_mg + tid * 33;
#pragma unroll
        for (int m = 0; m < 8; m++) {
            float xv = x[n * 8 + m];
            float e[4], sum = 0.f;
#pragma unroll
            for (int j = 0; j < 4; j++) {
                float d = xv - center[m * 4 + j];
                float sg = sigma[m * 4 + j];
                e[j] = __expf(-0.5f * d * d * sg * sg);
                sum += e[j];
            }
            float inv = 1.0f / sum;
#pragma unroll
            for (int j = 0; j < 4; j++) row[m * 4 + j] = e[j] * inv;
        }
    }

    // per-thread fragment-row state (group-independent):
    // thread owns sample rows w*32 + l/4 + {0,8,16,24}; rule digit j7 = l&3
    int srow = lane >> 2, j7 = lane & 3;
    const float* rs[4];
#pragma unroll
    for (int i = 0; i < 4; i++) rs[i] = s_mg + (w * 32 + srow + 8 * i) * 33;

    // ---- two rule groups per CTA ----
#pragma unroll 1
    for (int g2 = 0; g2 < 2; g2++) {
        int gy = blockIdx.y * 2 + g2;
        size_t gbase = (size_t)gy * 512;

        __syncthreads();   // g2=0: mg ready; g2=1: prev mainloop done with smB

        // ---- build B fragments straight from gmem ----
        // smB[kt*64 + nt*32 + l] = {tf32(Wb[8kt+l%4][n]), tf32(Wb[8kt+l%4+4][n])},
        // n = nt*8 + l/4
#pragma unroll 4
        for (int idx = tid; idx < 4096; idx += 128) {
            int kt = idx >> 6, rem = idx & 63;
            int l = rem & 31;
            int n = ((rem >> 5) << 3) + (l >> 2);
            int k0 = kt * 8 + (l & 3);
            float v0 = 0.f, v1 = 0.f;
            if (n < 8) {
                v0 = W[(gbase + k0) * 8 + n];
                v1 = W[(gbase + k0 + 4) * 8 + n];
            } else if (n == 8) {
                v0 = b[gbase + k0];
                v1 = b[gbase + k0 + 4];
            }
            smB[idx] = make_uint2(tf32r(v0), tf32r(v1));
        }
        __syncthreads();

        int j0 = (gy >> 5) & 3, j1 = (gy >> 3) & 3, j2 = (gy >> 1) & 3;
        float P0[4], m6r[4][4];
#pragma unroll
        for (int i = 0; i < 4; i++) {
            P0[i] = rs[i][j0] * rs[i][4 + j1] * rs[i][8 + j2] * rs[i][28 + j7];
#pragma unroll
            for (int j = 0; j < 4; j++) m6r[i][j] = rs[i][24 + j];
        }

        float d00[4] = {0,0,0,0}, d01[4] = {0,0,0,0};   // m-tile0, n-tile0/1
        float d10[4] = {0,0,0,0}, d11[4] = {0,0,0,0};   // m-tile1

        // ---- mainloop: 64 k-tiles of 8 rules ----
#pragma unroll 1
        for (int t3 = 0; t3 < 2; t3++) {
            int j3 = ((gy & 1) << 1) | t3;
            float b3[4];
#pragma unroll
            for (int i = 0; i < 4; i++) b3[i] = P0[i] * rs[i][12 + j3];
#pragma unroll 1
            for (int t4 = 0; t4 < 4; t4++) {
                float b4[4];
#pragma unroll
                for (int i = 0; i < 4; i++) b4[i] = b3[i] * rs[i][16 + t4];
                const uint2* Bbase = smB + (t3 * 32 + t4 * 8) * 64 + lane;
#pragma unroll
                for (int t5 = 0; t5 < 4; t5++) {
                    float b5[4];
#pragma unroll
                    for (int i = 0; i < 4; i++) b5[i] = b4[i] * rs[i][20 + t5];
#pragma unroll
                    for (int t6 = 0; t6 < 2; t6++) {
                        // raw f32 bits: HMMA truncates to tf32 in HW
                        uint32_t aLo[4], aHi[4];
#pragma unroll
                        for (int i = 0; i < 4; i++) {
                            aLo[i] = __float_as_uint(b5[i] * m6r[i][t6 * 2]);
                            aHi[i] = __float_as_uint(b5[i] * m6r[i][t6 * 2 + 1]);
                        }
                        const uint2* Bt = Bbase + (t5 * 2 + t6) * 64;
                        uint2 bf0 = Bt[0];       // n-tile 0
                        uint2 bf1 = Bt[32];      // n-tile 1 (bias col)
                        mma8(d00, aLo[0], aLo[1], aHi[0], aHi[1], bf0.x, bf0.y);
                        mma8(d01, aLo[0], aLo[1], aHi[0], aHi[1], bf1.x, bf1.y);
                        mma8(d10, aLo[2], aLo[3], aHi[2], aHi[3], bf0.x, bf0.y);
                        mma8(d11, aLo[2], aLo[3], aHi[2], aHi[3], bf1.x, bf1.y);
                    }
                }
            }
        }

        // ---- write partials: g_part[(gy*9+k)*NSAMP + n] ----
        {
            int k0 = j7 * 2;
            int n0 = tile * 128 + w * 32 + srow;
            float* gp = g_part + (size_t)gy * 9 * NSAMP;
            gp[(k0 + 0) * NSAMP + n0]      = d00[0];
            gp[(k0 + 1) * NSAMP + n0]      = d00[1];
            gp[(k0 + 0) * NSAMP + n0 + 8]  = d00[2];
            gp[(k0 + 1) * NSAMP + n0 + 8]  = d00[3];
            gp[(k0 + 0) * NSAMP + n0 + 16] = d10[0];
            gp[(k0 + 1) * NSAMP + n0 + 16] = d10[1];
            gp[(k0 + 0) * NSAMP + n0 + 24] = d10[2];
            gp[(k0 + 1) * NSAMP + n0 + 24] = d10[3];
            if (j7 == 0) {   // bias column
                gp[8 * NSAMP + n0]      = d01[0];
                gp[8 * NSAMP + n0 + 8]  = d01[2];
                gp[8 * NSAMP + n0 + 16] = d11[0];
                gp[8 * NSAMP + n0 + 24] = d11[2];
            }
        }
    }
}

// ---- reduce: A[k][n] = sum_g g_part[g][k][n]; one thread per (k,n) ----
__global__ __launch_bounds__(256) void reduce_kernel() {
    int id = blockIdx.x * 256 + threadIdx.x;   // id = k*NSAMP + n
    const float* p = g_part + id;
    float a0 = 0.f, a1 = 0.f, a2 = 0.f, a3 = 0.f;
    float a4 = 0.f, a5 = 0.f, a6 = 0.f, a7 = 0.f;
    const int stride = 9 * NSAMP;
#pragma unroll 2
    for (int g = 0; g < NGROUP; g += 8) {
        a0 += p[(g + 0) * stride];
        a1 += p[(g + 1) * stride];
        a2 += p[(g + 2) * stride];
        a3 += p[(g + 3) * stride];
        a4 += p[(g + 4) * stride];
        a5 += p[(g + 5) * stride];
        a6 += p[(g + 6) * stride];
        a7 += p[(g + 7) * stride];
    }
    g_A[id] = ((a0 + a1) + (a2 + a3)) + ((a4 + a5) + (a6 + a7));
}

// ---- out[n] = x[n]·A[:,n] + c[n] ----
__global__ __launch_bounds__(256) void out_kernel(const float* __restrict__ x,
                                                  float* __restrict__ out) {
    int n = blockIdx.x * 256 + threadIdx.x;
    float o = g_A[8 * NSAMP + n];
#pragma unroll
    for (int m = 0; m < 8; m++) o = fmaf(x[n * 8 + m], g_A[m * NSAMP + n], o);
    out[n] = o;
}

extern "C" void kernel_launch(void* const* d_in, const int* in_sizes, int n_in,
                              void* d_out, int out_size) {
    const float* x      = (const float*)d_in[0];
    const float* center = (const float*)d_in[1];
    const float* sigma  = (const float*)d_in[2];
    const float* W      = (const float*)d_in[3];
    const float* b      = (const float*)d_in[4];
    float* out = (float*)d_out;

    cudaFuncSetAttribute(tsk_kernel, cudaFuncAttributeMaxDynamicSharedMemorySize,
                         SMEM_TOTAL);
    dim3 grid(TILES, NGY);
    tsk_kernel<<<grid, 128, SMEM_TOTAL>>>(x, center, sigma, W, b);
    reduce_kernel<<<(9 * NSAMP) / 256, 256>>>();
    out_kernel<<<NSAMP / 256, 256>>>(x, out);
}

// round 13
// speedup vs baseline: 1.5471x; 1.5471x over previous
#include <cuda_runtime.h>
#include <cstdint>

// TSK fuzzy system via mma.sync tf32 tensor ops (baseline sm_80+ ISA).
// out[n] = sum_r fg_bar[n,r]*(x[n]·W[r]+b[r]); fg_bar separable-normalized:
// fg_bar[n,r] = prod_m mgn[n,m,digit_m(r)], mgn = mg/sum_j mg.
// Per CTA (tile of 128 samples, group of 512 rules):
//   D[128x16] = FG[128x512] @ Wb^T,  Wb[r] = [W[r][0..7], b[r], 0,...]
// FG fragments generated in registers and fed as RAW f32 bits (HW tf32
// truncation, no per-element cvt); Wb^T staged via smem, rna-cvt in prologue.

#define NSAMP 1024
#define NGROUP 128   // grid.y: rule groups of 512
#define TILES 8      // grid.x: sample tiles of 128

#define SM_UNION_OFF 32768
#define SMEM_TOTAL (32768 + 18432)

__device__ float g_part[NGROUP * 9 * NSAMP];  // [g][k][n]
__device__ float g_A[9 * NSAMP];              // [k][n] reduced

__device__ __forceinline__ uint32_t tf32r(float f) {
    uint32_t r; asm("cvt.rna.tf32.f32 %0, %1;" : "=r"(r) : "f"(f)); return r;
}
__device__ __forceinline__ void mma8(float* d, uint32_t a0, uint32_t a1,
                                     uint32_t a2, uint32_t a3,
                                     uint32_t b0, uint32_t b1) {
    asm volatile(
        "mma.sync.aligned.m16n8k8.row.col.f32.tf32.tf32.f32 "
        "{%0,%1,%2,%3}, {%4,%5,%6,%7}, {%8,%9}, {%0,%1,%2,%3};"
        : "+f"(d[0]), "+f"(d[1]), "+f"(d[2]), "+f"(d[3])
        : "r"(a0), "r"(a1), "r"(a2), "r"(a3), "r"(b0), "r"(b1));
}

__global__ __launch_bounds__(128) void tsk_kernel(
    const float* __restrict__ x, const float* __restrict__ center,
    const float* __restrict__ sigma, const float* __restrict__ W,
    const float* __restrict__ b)
{
    extern __shared__ __align__(16) unsigned char dynsm[];
    uint2* smB = reinterpret_cast<uint2*>(dynsm);               // B fragments
    float* uni = reinterpret_cast<float*>(dynsm + SM_UNION_OFF);

    int tid = threadIdx.x, lane = tid & 31, w = tid >> 5;
    int gy = blockIdx.y, tile = blockIdx.x;

    // ---- 1. raw Wb[r][0..8] into union (coalesced gmem loads) ----
#pragma unroll
    for (int q = 0; q < 4; q++) {
        int r = tid * 4 + q;
        size_t gr = (size_t)gy * 512 + r;
        float4 w0 = reinterpret_cast<const float4*>(W + gr * 8)[0];
        float4 w1 = reinterpret_cast<const float4*>(W + gr * 8)[1];
        float* row = uni + r * 9;
        row[0] = w0.x; row[1] = w0.y; row[2] = w0.z; row[3] = w0.w;
        row[4] = w1.x; row[5] = w1.y; row[6] = w1.z; row[7] = w1.w;
        row[8] = b[gr];
    }
    __syncthreads();

    // ---- 2. build B fragments from smem: smB[kt*64 + nt*32 + l] ----
    // = { tf32(Wb[8kt + l%4][n]), tf32(Wb[8kt + l%4 + 4][n]) }, n = nt*8 + l/4
#pragma unroll
    for (int idx = tid; idx < 4096; idx += 128) {
        int kt = idx >> 6, rem = idx & 63;
        int l = rem & 31;
        int n = ((rem >> 5) << 3) + (l >> 2);
        int k0 = kt * 8 + (l & 3);
        float v0 = (n < 9) ? uni[k0 * 9 + n] : 0.f;
        float v1 = (n < 9) ? uni[(k0 + 4) * 9 + n] : 0.f;
        smB[idx] = make_uint2(tf32r(v0), tf32r(v1));
    }
    __syncthreads();

    // ---- 3. memberships into union (overwrites raw Wb): [s][33] padded ----
    {
        int n = tile * 128 + tid;
        float* row = uni + tid * 33;
#pragma unroll
        for (int m = 0; m < 8; m++) {
            float xv = x[n * 8 + m];
            float e[4], sum = 0.f;
#pragma unroll
            for (int j = 0; j < 4; j++) {
                float d = xv - center[m * 4 + j];
                float sg = sigma[m * 4 + j];
                e[j] = __expf(-0.5f * d * d * sg * sg);
                sum += e[j];
            }
            float inv = 1.0f / sum;
#pragma unroll
            for (int j = 0; j < 4; j++) row[m * 4 + j] = e[j] * inv;
        }
    }
    __syncthreads();

    // ---- 4. per-thread fragment-row membership state ----
    // thread owns sample rows: w*32 + l/4 + {0,8,16,24}; rule digit j7 = l&3
    int srow = lane >> 2, j7 = lane & 3;
    const float* rs[4];
#pragma unroll
    for (int i = 0; i < 4; i++) rs[i] = uni + (w * 32 + srow + 8 * i) * 33;

    int j0 = (gy >> 5) & 3, j1 = (gy >> 3) & 3, j2 = (gy >> 1) & 3;
    float P0[4], m6r[4][4];
#pragma unroll
    for (int i = 0; i < 4; i++) {
        P0[i] = rs[i][j0] * rs[i][4 + j1] * rs[i][8 + j2] * rs[i][28 + j7];
#pragma unroll
        for (int j = 0; j < 4; j++) m6r[i][j] = rs[i][24 + j];
    }

    float d00[4] = {0,0,0,0}, d01[4] = {0,0,0,0};   // m-tile0, n-tile0/1
    float d10[4] = {0,0,0,0}, d11[4] = {0,0,0,0};   // m-tile1

    // ---- 5. mainloop: 64 k-tiles of 8 rules ----
#pragma unroll 1
    for (int t3 = 0; t3 < 2; t3++) {
        int j3 = ((gy & 1) << 1) | t3;
        float b3[4];
#pragma unroll
        for (int i = 0; i < 4; i++) b3[i] = P0[i] * rs[i][12 + j3];
#pragma unroll 1
        for (int t4 = 0; t4 < 4; t4++) {
            float b4[4];
#pragma unroll
            for (int i = 0; i < 4; i++) b4[i] = b3[i] * rs[i][16 + t4];
            const uint2* Bbase = smB + (t3 * 32 + t4 * 8) * 64 + lane;
#pragma unroll
            for (int t5 = 0; t5 < 4; t5++) {
                float b5[4];
#pragma unroll
                for (int i = 0; i < 4; i++) b5[i] = b4[i] * rs[i][20 + t5];
#pragma unroll
                for (int t6 = 0; t6 < 2; t6++) {
                    // raw f32 bits: HMMA truncates to tf32 in HW (no cvt)
                    uint32_t aLo[4], aHi[4];
#pragma unroll
                    for (int i = 0; i < 4; i++) {
                        aLo[i] = __float_as_uint(b5[i] * m6r[i][t6 * 2]);
                        aHi[i] = __float_as_uint(b5[i] * m6r[i][t6 * 2 + 1]);
                    }
                    const uint2* Bt = Bbase + (t5 * 2 + t6) * 64;
                    uint2 bf0 = Bt[0];       // n-tile 0
                    uint2 bf1 = Bt[32];      // n-tile 1 (bias col)
                    mma8(d00, aLo[0], aLo[1], aHi[0], aHi[1], bf0.x, bf0.y);
                    mma8(d01, aLo[0], aLo[1], aHi[0], aHi[1], bf1.x, bf1.y);
                    mma8(d10, aLo[2], aLo[3], aHi[2], aHi[3], bf0.x, bf0.y);
                    mma8(d11, aLo[2], aLo[3], aHi[2], aHi[3], bf1.x, bf1.y);
                }
            }
        }
    }

    // ---- 6. write partials: g_part[(gy*9+k)*NSAMP + n] ----
    {
        int k0 = j7 * 2;
        int n0 = tile * 128 + w * 32 + srow;
        float* gp = g_part + (size_t)gy * 9 * NSAMP;
        gp[(k0 + 0) * NSAMP + n0]      = d00[0];
        gp[(k0 + 1) * NSAMP + n0]      = d00[1];
        gp[(k0 + 0) * NSAMP + n0 + 8]  = d00[2];
        gp[(k0 + 1) * NSAMP + n0 + 8]  = d00[3];
        gp[(k0 + 0) * NSAMP + n0 + 16] = d10[0];
        gp[(k0 + 1) * NSAMP + n0 + 16] = d10[1];
        gp[(k0 + 0) * NSAMP + n0 + 24] = d10[2];
        gp[(k0 + 1) * NSAMP + n0 + 24] = d10[3];
        if (j7 == 0) {   // bias column
            gp[8 * NSAMP + n0]      = d01[0];
            gp[8 * NSAMP + n0 + 8]  = d01[2];
            gp[8 * NSAMP + n0 + 16] = d11[0];
            gp[8 * NSAMP + n0 + 24] = d11[2];
        }
    }
}

// ---- reduce: A[k][n] = sum_g g_part[g][k][n]; one thread per (k,n) ----
__global__ __launch_bounds__(256) void reduce_kernel() {
    int id = blockIdx.x * 256 + threadIdx.x;   // id = k*NSAMP + n
    const float* p = g_part + id;
    float a0 = 0.f, a1 = 0.f, a2 = 0.f, a3 = 0.f;
    float a4 = 0.f, a5 = 0.f, a6 = 0.f, a7 = 0.f;
    const int stride = 9 * NSAMP;
#pragma unroll 2
    for (int g = 0; g < NGROUP; g += 8) {
        a0 += p[(g + 0) * stride];
        a1 += p[(g + 1) * stride];
        a2 += p[(g + 2) * stride];
        a3 += p[(g + 3) * stride];
        a4 += p[(g + 4) * stride];
        a5 += p[(g + 5) * stride];
        a6 += p[(g + 6) * stride];
        a7 += p[(g + 7) * stride];
    }
    g_A[id] = ((a0 + a1) + (a2 + a3)) + ((a4 + a5) + (a6 + a7));
}

// ---- out[n] = x[n]·A[:,n] + c[n] ----
__global__ __launch_bounds__(256) void out_kernel(const float* __restrict__ x,
                                                  float* __restrict__ out) {
    int n = blockIdx.x * 256 + threadIdx.x;
    float o = g_A[8 * NSAMP + n];
#pragma unroll
    for (int m = 0; m < 8; m++) o = fmaf(x[n * 8 + m], g_A[m * NSAMP + n], o);
    out[n] = o;
}

extern "C" void kernel_launch(void* const* d_in, const int* in_sizes, int n_in,
                              void* d_out, int out_size) {
    const float* x      = (const float*)d_in[0];
    const float* center = (const float*)d_in[1];
    const float* sigma  = (const float*)d_in[2];
    const float* W      = (const float*)d_in[3];
    const float* b      = (const float*)d_in[4];
    float* out = (float*)d_out;

    cudaFuncSetAttribute(tsk_kernel, cudaFuncAttributeMaxDynamicSharedMemorySize,
                         SMEM_TOTAL);
    dim3 grid(TILES, NGROUP);
    tsk_kernel<<<grid, 128, SMEM_TOTAL>>>(x, center, sigma, W, b);
    reduce_kernel<<<(9 * NSAMP) / 256, 256>>>();
    out_kernel<<<NSAMP / 256, 256>>>(x, out);
}

// round 14
// speedup vs baseline: 1.6503x; 1.0667x over previous
#include <cuda_runtime.h>
#include <cstdint>

// TSK fuzzy system via mma.sync tf32 tensor ops (baseline sm_80+ ISA).
// out[n] = sum_r fg_bar[n,r]*(x[n]·W[r]+b[r]); fg_bar separable-normalized.
// Per CTA (tile of 128 samples, group of 512 rules):
//   D[128x16] = FG[128x512] @ Wb^T,  Wb[r] = [W[r][0..7], b[r], 0,...]
// 256 threads = 8 warps; each warp owns one 16-row m-tile (2 samples/lane,
// which are exactly A-fragment rows srow/srow+8). fg chain computed with
// packed f32x2 over the sample pair; raw f32 bits fed to HMMA (HW tf32
// truncation). Wb^T staged via smem; rna-cvt only in prologue.

#define NSAMP 1024
#define NGROUP 128   // grid.y: rule groups of 512
#define TILES 8      // grid.x: sample tiles of 128

#define SM_UNION_OFF 32768
#define SMEM_TOTAL (32768 + 18432)

typedef unsigned long long ull;

__device__ float g_part[NGROUP * 9 * NSAMP];  // [g][k][n]
__device__ float g_A[9 * NSAMP];              // [k][n] reduced

__device__ __forceinline__ uint32_t tf32r(float f) {
    uint32_t r; asm("cvt.rna.tf32.f32 %0, %1;" : "=r"(r) : "f"(f)); return r;
}
__device__ __forceinline__ ull pack2f(float a, float b) {
    ull r; asm("mov.b64 %0, {%1, %2};" : "=l"(r) : "f"(a), "f"(b)); return r;
}
__device__ __forceinline__ ull mul2(ull a, ull b) {
    ull d; asm("mul.rn.f32x2 %0, %1, %2;" : "=l"(d) : "l"(a), "l"(b)); return d;
}
__device__ __forceinline__ void unpack2u(ull v, uint32_t& a, uint32_t& b) {
    asm("mov.b64 {%0, %1}, %2;" : "=r"(a), "=r"(b) : "l"(v));
}
__device__ __forceinline__ void mma8(float* d, uint32_t a0, uint32_t a1,
                                     uint32_t a2, uint32_t a3,
                                     uint32_t b0, uint32_t b1) {
    asm volatile(
        "mma.sync.aligned.m16n8k8.row.col.f32.tf32.tf32.f32 "
        "{%0,%1,%2,%3}, {%4,%5,%6,%7}, {%8,%9}, {%0,%1,%2,%3};"
        : "+f"(d[0]), "+f"(d[1]), "+f"(d[2]), "+f"(d[3])
        : "r"(a0), "r"(a1), "r"(a2), "r"(a3), "r"(b0), "r"(b1));
}

__global__ __launch_bounds__(256) void tsk_kernel(
    const float* __restrict__ x, const float* __restrict__ center,
    const float* __restrict__ sigma, const float* __restrict__ W,
    const float* __restrict__ b)
{
    extern __shared__ __align__(16) unsigned char dynsm[];
    uint2* smB = reinterpret_cast<uint2*>(dynsm);               // B fragments
    float* uni = reinterpret_cast<float*>(dynsm + SM_UNION_OFF);

    int tid = threadIdx.x, lane = tid & 31, w = tid >> 5;
    int gy = blockIdx.y, tile = blockIdx.x;

    // ---- 1. raw Wb[r][0..8] into union (coalesced gmem loads) ----
#pragma unroll
    for (int q = 0; q < 2; q++) {
        int r = tid * 2 + q;
        size_t gr = (size_t)gy * 512 + r;
        float4 w0 = reinterpret_cast<const float4*>(W + gr * 8)[0];
        float4 w1 = reinterpret_cast<const float4*>(W + gr * 8)[1];
        float* row = uni + r * 9;
        row[0] = w0.x; row[1] = w0.y; row[2] = w0.z; row[3] = w0.w;
        row[4] = w1.x; row[5] = w1.y; row[6] = w1.z; row[7] = w1.w;
        row[8] = b[gr];
    }
    __syncthreads();

    // ---- 2. build B fragments from smem: smB[kt*64 + nt*32 + l] ----
    // = { tf32(Wb[8kt + l%4][n]), tf32(Wb[8kt + l%4 + 4][n]) }, n = nt*8 + l/4
#pragma unroll
    for (int idx = tid; idx < 4096; idx += 256) {
        int kt = idx >> 6, rem = idx & 63;
        int l = rem & 31;
        int n = ((rem >> 5) << 3) + (l >> 2);
        int k0 = kt * 8 + (l & 3);
        float v0 = (n < 9) ? uni[k0 * 9 + n] : 0.f;
        float v1 = (n < 9) ? uni[(k0 + 4) * 9 + n] : 0.f;
        smB[idx] = make_uint2(tf32r(v0), tf32r(v1));
    }
    __syncthreads();

    // ---- 3. memberships into union (overwrites raw Wb): [s][33] padded ----
    // 2 threads per sample: s = tid&127 handles dims mh*4..mh*4+3
    {
        int s = tid & 127, mh = tid >> 7;
        int n = tile * 128 + s;
        float4 xv4 = *reinterpret_cast<const float4*>(x + n * 8 + mh * 4);
        float xv[4] = {xv4.x, xv4.y, xv4.z, xv4.w};
        float* row = uni + s * 33;
#pragma unroll
        for (int mm = 0; mm < 4; mm++) {
            int m = mh * 4 + mm;
            float e[4], sum = 0.f;
#pragma unroll
            for (int j = 0; j < 4; j++) {
                float d = xv[mm] - center[m * 4 + j];
                float sg = sigma[m * 4 + j];
                e[j] = __expf(-0.5f * d * d * sg * sg);
                sum += e[j];
            }
            float inv = 1.0f / sum;
#pragma unroll
            for (int j = 0; j < 4; j++) row[m * 4 + j] = e[j] * inv;
        }
    }
    __syncthreads();

    // ---- 4. per-thread state: warp w owns rows w*16..w*16+15 ----
    // lane's samples: srow = lane/4 and srow+8  (A-fragment rows); j7 = lane&3
    int srow = lane >> 2, j7 = lane & 3;
    const float* r0 = uni + (w * 16 + srow) * 33;
    const float* r1 = r0 + 8 * 33;

    int j0 = (gy >> 5) & 3, j1 = (gy >> 3) & 3, j2 = (gy >> 1) & 3;
    float pA = r0[j0] * r0[4 + j1] * r0[8 + j2] * r0[28 + j7];
    float pB = r1[j0] * r1[4 + j1] * r1[8 + j2] * r1[28 + j7];
    ull pre = pack2f(pA, pB);

    int j3b = (gy & 1) << 1;
    ull pm3[2], pm4[4], pm5[4], pm6[4];
#pragma unroll
    for (int t = 0; t < 2; t++) pm3[t] = pack2f(r0[12 + j3b + t], r1[12 + j3b + t]);
#pragma unroll
    for (int j = 0; j < 4; j++) {
        pm4[j] = pack2f(r0[16 + j], r1[16 + j]);
        pm5[j] = pack2f(r0[20 + j], r1[20 + j]);
        pm6[j] = pack2f(r0[24 + j], r1[24 + j]);
    }

    float d00[4] = {0,0,0,0};   // n-tile0 (W cols 0-7)
    float d01[4] = {0,0,0,0};   // n-tile1 (bias col 8)

    // ---- 5. mainloop: 64 k-tiles of 8 rules ----
#pragma unroll 1
    for (int t3 = 0; t3 < 2; t3++) {
        ull b3 = mul2(pre, pm3[t3]);
#pragma unroll 1
        for (int t4 = 0; t4 < 4; t4++) {
            ull b4 = mul2(b3, pm4[t4]);
            const uint2* Bbase = smB + (t3 * 32 + t4 * 8) * 64 + lane;
#pragma unroll
            for (int t5 = 0; t5 < 4; t5++) {
                ull b5 = mul2(b4, pm5[t5]);
#pragma unroll
                for (int t6 = 0; t6 < 2; t6++) {
                    // {a0,a1} = fg rows (srow, srow+8) at col j7 (j6 = 2t6)
                    // {a2,a3} = same rows at col j7+4    (j6 = 2t6+1)
                    ull alo = mul2(b5, pm6[2 * t6]);
                    ull ahi = mul2(b5, pm6[2 * t6 + 1]);
                    uint32_t a0, a1, a2, a3;
                    unpack2u(alo, a0, a1);
                    unpack2u(ahi, a2, a3);
                    const uint2* Bt = Bbase + (t5 * 2 + t6) * 64;
                    uint2 bf0 = Bt[0];       // n-tile 0
                    uint2 bf1 = Bt[32];      // n-tile 1 (bias col)
                    mma8(d00, a0, a1, a2, a3, bf0.x, bf0.y);
                    mma8(d01, a0, a1, a2, a3, bf1.x, bf1.y);
                }
            }
        }
    }

    // ---- 6. write partials: g_part[(gy*9+k)*NSAMP + n] ----
    {
        int k0 = j7 * 2;
        int n0 = tile * 128 + w * 16 + srow;
        float* gp = g_part + (size_t)gy * 9 * NSAMP;
        gp[(k0 + 0) * NSAMP + n0]     = d00[0];
        gp[(k0 + 1) * NSAMP + n0]     = d00[1];
        gp[(k0 + 0) * NSAMP + n0 + 8] = d00[2];
        gp[(k0 + 1) * NSAMP + n0 + 8] = d00[3];
        if (j7 == 0) {   // bias column (col 8 = n-tile1 col 0)
            gp[8 * NSAMP + n0]     = d01[0];
            gp[8 * NSAMP + n0 + 8] = d01[2];
        }
    }
}

// ---- reduce: A[k][n] = sum_g g_part[g][k][n]; one thread per (k,n) ----
__global__ __launch_bounds__(256) void reduce_kernel() {
    int id = blockIdx.x * 256 + threadIdx.x;   // id = k*NSAMP + n
    const float* p = g_part + id;
    float a0 = 0.f, a1 = 0.f, a2 = 0.f, a3 = 0.f;
    float a4 = 0.f, a5 = 0.f, a6 = 0.f, a7 = 0.f;
    const int stride = 9 * NSAMP;
#pragma unroll 2
    for (int g = 0; g < NGROUP; g += 8) {
        a0 += p[(g + 0) * stride];
        a1 += p[(g + 1) * stride];
        a2 += p[(g + 2) * stride];
        a3 += p[(g + 3) * stride];
        a4 += p[(g + 4) * stride];
        a5 += p[(g + 5) * stride];
        a6 += p[(g + 6) * stride];
        a7 += p[(g + 7) * stride];
    }
    g_A[id] = ((a0 + a1) + (a2 + a3)) + ((a4 + a5) + (a6 + a7));
}

// ---- out[n] = x[n]·A[:,n] + c[n] ----
__global__ __launch_bounds__(256) void out_kernel(const float* __restrict__ x,
                                                  float* __restrict__ out) {
    int n = blockIdx.x * 256 + threadIdx.x;
    float o = g_A[8 * NSAMP + n];
#pragma unroll
    for (int m = 0; m < 8; m++) o = fmaf(x[n * 8 + m], g_A[m * NSAMP + n], o);
    out[n] = o;
}

extern "C" void kernel_launch(void* const* d_in, const int* in_sizes, int n_in,
                              void* d_out, int out_size) {
    const float* x      = (const float*)d_in[0];
    const float* center = (const float*)d_in[1];
    const float* sigma  = (const float*)d_in[2];
    const float* W      = (const float*)d_in[3];
    const float* b      = (const float*)d_in[4];
    float* out = (float*)d_out;

    cudaFuncSetAttribute(tsk_kernel, cudaFuncAttributeMaxDynamicSharedMemorySize,
                         SMEM_TOTAL);
    dim3 grid(TILES, NGROUP);
    tsk_kernel<<<grid, 256, SMEM_TOTAL>>>(x, center, sigma, W, b);
    reduce_kernel<<<(9 * NSAMP) / 256, 256>>>();
    out_kernel<<<NSAMP / 256, 256>>>(x, out);
}